// round 12
// baseline (speedup 1.0000x reference)
#include <cuda_runtime.h>
#include <cuda_bf16.h>
#include <cstdint>

// ============================================================================
// ReLU15Loss — FINAL (converged at the HBM streaming ceiling)
//
// loss = mean_rows[ (2/3) * sum_j tp^2*(tp+2) - (x[r,tgt_r] - 2*tau) ],
//   tp = max(0.5x - tau, 0). Single pass over X (1.048 GB), one fused kernel.
//
// Config sweep (kernel dur / DRAM%):
//   16 KB chunk, 64000x128: 227 us / 58%  (CTA-churn starved)
//   32 KB chunk, 32000x256: 145.5-148.6 us / 89-91%   <== THIS
//   40 KB chunk, 25600x256: 146.3 us / 90.7%
//   64 KB chunk, 16000x512: 146.8 us / 90.4%
//  128 KB row,    8192x256: 149.8 us / 88.7%
//  persistent 1184-CTA grid-stride: 156.7 us / 84.8%
// Plateau ~7.2 TB/s = 90% HBM spec; LTS cap is path-independent (TMA same).
// ============================================================================

#define N_ROWS      8192
#define NUM_CLASSES 32000
#define TOTAL_VEC   65536000u      // 8192*32000/4 float4
#define TAU         0.05f
#define THREADS     256
#define CHUNK_VEC   2048u          // vec4 per CTA = 32 KB (8 loads/thread)
#define GRID        32000u         // TOTAL_VEC / CHUNK_VEC (exact)

// Device-global scratch (no cudaMalloc allowed).
__device__ double       g_loss_sum = 0.0;
__device__ unsigned int g_done     = 0;   // atomicInc auto-wraps to 0

__device__ __forceinline__ float relu15_term(float x) {
    float t = fmaxf(fmaf(0.5f, x, -TAU), 0.0f);
    return t * t * (t + 2.0f);
}

__device__ __forceinline__ float relu15_vec4(float4 v) {
    return relu15_term(v.x) + relu15_term(v.y) +
           relu15_term(v.z) + relu15_term(v.w);
}

__global__ __launch_bounds__(THREADS, 8)
void relu15_chunk_kernel(const float* __restrict__ X,
                         const int* __restrict__ target,
                         float* __restrict__ out) {
    const float4* __restrict__ xv = reinterpret_cast<const float4*>(X);
    const unsigned base = blockIdx.x * CHUNK_VEC + threadIdx.x;

    // Exactly 8 vec4 per thread, fully unrolled -> 8 front-batched LDG.128.
    float4 v0 = __ldcs(xv + base + 0 * THREADS);
    float4 v1 = __ldcs(xv + base + 1 * THREADS);
    float4 v2 = __ldcs(xv + base + 2 * THREADS);
    float4 v3 = __ldcs(xv + base + 3 * THREADS);
    float4 v4 = __ldcs(xv + base + 4 * THREADS);
    float4 v5 = __ldcs(xv + base + 5 * THREADS);
    float4 v6 = __ldcs(xv + base + 6 * THREADS);
    float4 v7 = __ldcs(xv + base + 7 * THREADS);

    float a0 = relu15_vec4(v0) + relu15_vec4(v4);
    float a1 = relu15_vec4(v1) + relu15_vec4(v5);
    float a2 = relu15_vec4(v2) + relu15_vec4(v6);
    float a3 = relu15_vec4(v3) + relu15_vec4(v7);

    float acc = ((a0 + a1) + (a2 + a3)) * (2.0f / 3.0f);

    // Target correction: first 8192 global threads each handle one row.
    const unsigned gtid = blockIdx.x * THREADS + threadIdx.x;
    if (gtid < N_ROWS) {
        int tgt = target[gtid];
        tgt = min(max(tgt, 0), NUM_CLASSES - 1);   // defensive clamp
        float xt = __ldg(X + (size_t)gtid * NUM_CLASSES + (size_t)tgt);
        acc -= (xt - 2.0f * TAU);
    }

    // Warp reduce
    #pragma unroll
    for (int off = 16; off > 0; off >>= 1)
        acc += __shfl_down_sync(0xFFFFFFFFu, acc, off);

    __shared__ float warp_sums[THREADS / 32];
    const int lane = threadIdx.x & 31;
    const int wid  = threadIdx.x >> 5;
    if (lane == 0) warp_sums[wid] = acc;
    __syncthreads();

    if (wid == 0) {
        float s = (lane < THREADS / 32) ? warp_sums[lane] : 0.0f;
        #pragma unroll
        for (int off = 4; off > 0; off >>= 1)
            s += __shfl_down_sync(0xFFFFFFFFu, s, off);

        if (lane == 0) {
            atomicAdd(&g_loss_sum, (double)s);
            __threadfence();

            // Completion counter wraps to 0 at GRID-1 (auto reset per replay).
            unsigned int prev = atomicInc(&g_done, GRID - 1);
            if (prev == GRID - 1) {
                __threadfence();
                double total = g_loss_sum;
                out[0] = (float)(total / (double)N_ROWS);
                g_loss_sum = 0.0;          // reset for next graph replay
                __threadfence();
            }
        }
    }
}

extern "C" void kernel_launch(void* const* d_in, const int* in_sizes, int n_in,
                              void* d_out, int out_size) {
    const float* X      = (const float*)d_in[0];
    const int*   target = (const int*)d_in[1];
    float*       out    = (float*)d_out;

    relu15_chunk_kernel<<<GRID, THREADS>>>(X, target, out);
}

// round 13
// speedup vs baseline: 1.0046x; 1.0046x over previous
#include <cuda_runtime.h>
#include <cuda_bf16.h>
#include <cstdint>

// ============================================================================
// ReLU15Loss — FINAL (converged at the HBM streaming ceiling)
//
// loss = mean_rows[ (2/3) * sum_j tp^2*(tp+2) - (x[r,tgt_r] - 2*tau) ],
//   tp = max(0.5x - tau, 0). Single pass over X (1.048 GB), one fused kernel.
//
// Config sweep (bench / kernel DRAM%):
//   16 KB chunk, 64000x128: 221 us / 58%   (CTA-churn starved)
//   32 KB chunk, 32000x256: 146.2-147.6 us / 89-91%   <== THIS (best)
//   40 KB chunk, 25600x256: 146.3 us / 90.7%
//   64 KB chunk, 16000x512: 147.2 us / 90.4%
//  128 KB row,    8192x256: 149.9 us / 88.7%
//  persistent 1184-CTA grid-stride: 151.6 us / 84.8%
// Plateau ~7.2 TB/s = 90% of HBM spec; LTS cap is path-independent (a TMA
// rewrite hits the same wall). Remaining deltas are run-to-run noise.
// ============================================================================

#define N_ROWS      8192
#define NUM_CLASSES 32000
#define TOTAL_VEC   65536000u      // 8192*32000/4 float4
#define TAU         0.05f
#define THREADS     256
#define CHUNK_VEC   2048u          // vec4 per CTA = 32 KB (8 loads/thread)
#define GRID        32000u         // TOTAL_VEC / CHUNK_VEC (exact)

// Device-global scratch (no cudaMalloc allowed).
__device__ double       g_loss_sum = 0.0;
__device__ unsigned int g_done     = 0;   // atomicInc auto-wraps to 0

__device__ __forceinline__ float relu15_term(float x) {
    float t = fmaxf(fmaf(0.5f, x, -TAU), 0.0f);
    return t * t * (t + 2.0f);
}

__device__ __forceinline__ float relu15_vec4(float4 v) {
    return relu15_term(v.x) + relu15_term(v.y) +
           relu15_term(v.z) + relu15_term(v.w);
}

__global__ __launch_bounds__(THREADS, 8)
void relu15_chunk_kernel(const float* __restrict__ X,
                         const int* __restrict__ target,
                         float* __restrict__ out) {
    const float4* __restrict__ xv = reinterpret_cast<const float4*>(X);
    const unsigned base = blockIdx.x * CHUNK_VEC + threadIdx.x;

    // Exactly 8 vec4 per thread, fully unrolled -> 8 front-batched LDG.128.
    float4 v0 = __ldcs(xv + base + 0 * THREADS);
    float4 v1 = __ldcs(xv + base + 1 * THREADS);
    float4 v2 = __ldcs(xv + base + 2 * THREADS);
    float4 v3 = __ldcs(xv + base + 3 * THREADS);
    float4 v4 = __ldcs(xv + base + 4 * THREADS);
    float4 v5 = __ldcs(xv + base + 5 * THREADS);
    float4 v6 = __ldcs(xv + base + 6 * THREADS);
    float4 v7 = __ldcs(xv + base + 7 * THREADS);

    float a0 = relu15_vec4(v0) + relu15_vec4(v4);
    float a1 = relu15_vec4(v1) + relu15_vec4(v5);
    float a2 = relu15_vec4(v2) + relu15_vec4(v6);
    float a3 = relu15_vec4(v3) + relu15_vec4(v7);

    float acc = ((a0 + a1) + (a2 + a3)) * (2.0f / 3.0f);

    // Target correction: first 8192 global threads each handle one row.
    const unsigned gtid = blockIdx.x * THREADS + threadIdx.x;
    if (gtid < N_ROWS) {
        int tgt = target[gtid];
        tgt = min(max(tgt, 0), NUM_CLASSES - 1);   // defensive clamp
        float xt = __ldg(X + (size_t)gtid * NUM_CLASSES + (size_t)tgt);
        acc -= (xt - 2.0f * TAU);
    }

    // Warp reduce
    #pragma unroll
    for (int off = 16; off > 0; off >>= 1)
        acc += __shfl_down_sync(0xFFFFFFFFu, acc, off);

    __shared__ float warp_sums[THREADS / 32];
    const int lane = threadIdx.x & 31;
    const int wid  = threadIdx.x >> 5;
    if (lane == 0) warp_sums[wid] = acc;
    __syncthreads();

    if (wid == 0) {
        float s = (lane < THREADS / 32) ? warp_sums[lane] : 0.0f;
        #pragma unroll
        for (int off = 4; off > 0; off >>= 1)
            s += __shfl_down_sync(0xFFFFFFFFu, s, off);

        if (lane == 0) {
            atomicAdd(&g_loss_sum, (double)s);
            __threadfence();

            // Completion counter wraps to 0 at GRID-1 (auto reset per replay).
            unsigned int prev = atomicInc(&g_done, GRID - 1);
            if (prev == GRID - 1) {
                __threadfence();
                double total = g_loss_sum;
                out[0] = (float)(total / (double)N_ROWS);
                g_loss_sum = 0.0;          // reset for next graph replay
                __threadfence();
            }
        }
    }
}

extern "C" void kernel_launch(void* const* d_in, const int* in_sizes, int n_in,
                              void* d_out, int out_size) {
    const float* X      = (const float*)d_in[0];
    const int*   target = (const int*)d_in[1];
    float*       out    = (float*)d_out;

    relu15_chunk_kernel<<<GRID, THREADS>>>(X, target, out);
}

// round 14
// speedup vs baseline: 1.0112x; 1.0066x over previous
#include <cuda_runtime.h>
#include <cuda_bf16.h>
#include <cstdint>

// ============================================================================
// ReLU15Loss — FINAL (converged at the HBM streaming ceiling)
//
// loss = mean_rows[ (2/3) * sum_j tp^2*(tp+2) - (x[r,tgt_r] - 2*tau) ],
//   tp = max(0.5x - tau, 0). Single pass over X (1.048 GB), one fused kernel.
//
// Config sweep (bench / kernel DRAM%):
//   16 KB chunk, 64000x128: 221 us / 58%   (CTA-churn starved)
//   32 KB chunk, 32000x256: 146.2-147.6 us / 89-91%   <== THIS (best)
//   40 KB chunk, 25600x256: 146.3 us / 90.7%
//   64 KB chunk, 16000x512: 147.2 us / 90.4%
//  128 KB row,    8192x256: 149.9 us / 88.7%
//  persistent 1184-CTA grid-stride: 151.6 us / 84.8%
// Plateau ~7.2 TB/s = 90% of HBM spec; LTS cap is path-independent (a TMA
// rewrite hits the same wall). Remaining deltas are run-to-run noise.
// ============================================================================

#define N_ROWS      8192
#define NUM_CLASSES 32000
#define TOTAL_VEC   65536000u      // 8192*32000/4 float4
#define TAU         0.05f
#define THREADS     256
#define CHUNK_VEC   2048u          // vec4 per CTA = 32 KB (8 loads/thread)
#define GRID        32000u         // TOTAL_VEC / CHUNK_VEC (exact)

// Device-global scratch (no cudaMalloc allowed).
__device__ double       g_loss_sum = 0.0;
__device__ unsigned int g_done     = 0;   // atomicInc auto-wraps to 0

__device__ __forceinline__ float relu15_term(float x) {
    float t = fmaxf(fmaf(0.5f, x, -TAU), 0.0f);
    return t * t * (t + 2.0f);
}

__device__ __forceinline__ float relu15_vec4(float4 v) {
    return relu15_term(v.x) + relu15_term(v.y) +
           relu15_term(v.z) + relu15_term(v.w);
}

__global__ __launch_bounds__(THREADS, 8)
void relu15_chunk_kernel(const float* __restrict__ X,
                         const int* __restrict__ target,
                         float* __restrict__ out) {
    const float4* __restrict__ xv = reinterpret_cast<const float4*>(X);
    const unsigned base = blockIdx.x * CHUNK_VEC + threadIdx.x;

    // Exactly 8 vec4 per thread, fully unrolled -> 8 front-batched LDG.128.
    float4 v0 = __ldcs(xv + base + 0 * THREADS);
    float4 v1 = __ldcs(xv + base + 1 * THREADS);
    float4 v2 = __ldcs(xv + base + 2 * THREADS);
    float4 v3 = __ldcs(xv + base + 3 * THREADS);
    float4 v4 = __ldcs(xv + base + 4 * THREADS);
    float4 v5 = __ldcs(xv + base + 5 * THREADS);
    float4 v6 = __ldcs(xv + base + 6 * THREADS);
    float4 v7 = __ldcs(xv + base + 7 * THREADS);

    float a0 = relu15_vec4(v0) + relu15_vec4(v4);
    float a1 = relu15_vec4(v1) + relu15_vec4(v5);
    float a2 = relu15_vec4(v2) + relu15_vec4(v6);
    float a3 = relu15_vec4(v3) + relu15_vec4(v7);

    float acc = ((a0 + a1) + (a2 + a3)) * (2.0f / 3.0f);

    // Target correction: first 8192 global threads each handle one row.
    const unsigned gtid = blockIdx.x * THREADS + threadIdx.x;
    if (gtid < N_ROWS) {
        int tgt = target[gtid];
        tgt = min(max(tgt, 0), NUM_CLASSES - 1);   // defensive clamp
        float xt = __ldg(X + (size_t)gtid * NUM_CLASSES + (size_t)tgt);
        acc -= (xt - 2.0f * TAU);
    }

    // Warp reduce
    #pragma unroll
    for (int off = 16; off > 0; off >>= 1)
        acc += __shfl_down_sync(0xFFFFFFFFu, acc, off);

    __shared__ float warp_sums[THREADS / 32];
    const int lane = threadIdx.x & 31;
    const int wid  = threadIdx.x >> 5;
    if (lane == 0) warp_sums[wid] = acc;
    __syncthreads();

    if (wid == 0) {
        float s = (lane < THREADS / 32) ? warp_sums[lane] : 0.0f;
        #pragma unroll
        for (int off = 4; off > 0; off >>= 1)
            s += __shfl_down_sync(0xFFFFFFFFu, s, off);

        if (lane == 0) {
            atomicAdd(&g_loss_sum, (double)s);
            __threadfence();

            // Completion counter wraps to 0 at GRID-1 (auto reset per replay).
            unsigned int prev = atomicInc(&g_done, GRID - 1);
            if (prev == GRID - 1) {
                __threadfence();
                double total = g_loss_sum;
                out[0] = (float)(total / (double)N_ROWS);
                g_loss_sum = 0.0;          // reset for next graph replay
                __threadfence();
            }
        }
    }
}

extern "C" void kernel_launch(void* const* d_in, const int* in_sizes, int n_in,
                              void* d_out, int out_size) {
    const float* X      = (const float*)d_in[0];
    const int*   target = (const int*)d_in[1];
    float*       out    = (float*)d_out;

    relu15_chunk_kernel<<<GRID, THREADS>>>(X, target, out);
}

// round 15
// speedup vs baseline: 1.0143x; 1.0031x over previous
#include <cuda_runtime.h>
#include <cuda_bf16.h>
#include <cstdint>

// ============================================================================
// ReLU15Loss — FINAL (converged at the HBM streaming ceiling)
//
// loss = mean_rows[ (2/3) * sum_j tp^2*(tp+2) - (x[r,tgt_r] - 2*tau) ],
//   tp = max(0.5x - tau, 0). Single pass over X (1.048 GB), one fused kernel.
//
// Config sweep (bench / kernel DRAM%):
//   16 KB chunk, 64000x128: 221 us / 58%   (CTA-churn starved)
//   32 KB chunk, 32000x256: 146.0-147.6 us / 89-91%   <== THIS (best)
//   40 KB chunk, 25600x256: 146.3 us / 90.7%
//   64 KB chunk, 16000x512: 147.2 us / 90.4%
//  128 KB row,    8192x256: 149.9 us / 88.7%
//  persistent 1184-CTA grid-stride: 151.6 us / 84.8%
// Plateau ~7.2 TB/s = 90% of HBM spec; LTS cap is path-independent (a TMA
// rewrite hits the same wall). Remaining deltas are run-to-run noise.
// ============================================================================

#define N_ROWS      8192
#define NUM_CLASSES 32000
#define TOTAL_VEC   65536000u      // 8192*32000/4 float4
#define TAU         0.05f
#define THREADS     256
#define CHUNK_VEC   2048u          // vec4 per CTA = 32 KB (8 loads/thread)
#define GRID        32000u         // TOTAL_VEC / CHUNK_VEC (exact)

// Device-global scratch (no cudaMalloc allowed).
__device__ double       g_loss_sum = 0.0;
__device__ unsigned int g_done     = 0;   // atomicInc auto-wraps to 0

__device__ __forceinline__ float relu15_term(float x) {
    float t = fmaxf(fmaf(0.5f, x, -TAU), 0.0f);
    return t * t * (t + 2.0f);
}

__device__ __forceinline__ float relu15_vec4(float4 v) {
    return relu15_term(v.x) + relu15_term(v.y) +
           relu15_term(v.z) + relu15_term(v.w);
}

__global__ __launch_bounds__(THREADS, 8)
void relu15_chunk_kernel(const float* __restrict__ X,
                         const int* __restrict__ target,
                         float* __restrict__ out) {
    const float4* __restrict__ xv = reinterpret_cast<const float4*>(X);
    const unsigned base = blockIdx.x * CHUNK_VEC + threadIdx.x;

    // Exactly 8 vec4 per thread, fully unrolled -> 8 front-batched LDG.128.
    float4 v0 = __ldcs(xv + base + 0 * THREADS);
    float4 v1 = __ldcs(xv + base + 1 * THREADS);
    float4 v2 = __ldcs(xv + base + 2 * THREADS);
    float4 v3 = __ldcs(xv + base + 3 * THREADS);
    float4 v4 = __ldcs(xv + base + 4 * THREADS);
    float4 v5 = __ldcs(xv + base + 5 * THREADS);
    float4 v6 = __ldcs(xv + base + 6 * THREADS);
    float4 v7 = __ldcs(xv + base + 7 * THREADS);

    float a0 = relu15_vec4(v0) + relu15_vec4(v4);
    float a1 = relu15_vec4(v1) + relu15_vec4(v5);
    float a2 = relu15_vec4(v2) + relu15_vec4(v6);
    float a3 = relu15_vec4(v3) + relu15_vec4(v7);

    float acc = ((a0 + a1) + (a2 + a3)) * (2.0f / 3.0f);

    // Target correction: first 8192 global threads each handle one row.
    const unsigned gtid = blockIdx.x * THREADS + threadIdx.x;
    if (gtid < N_ROWS) {
        int tgt = target[gtid];
        tgt = min(max(tgt, 0), NUM_CLASSES - 1);   // defensive clamp
        float xt = __ldg(X + (size_t)gtid * NUM_CLASSES + (size_t)tgt);
        acc -= (xt - 2.0f * TAU);
    }

    // Warp reduce
    #pragma unroll
    for (int off = 16; off > 0; off >>= 1)
        acc += __shfl_down_sync(0xFFFFFFFFu, acc, off);

    __shared__ float warp_sums[THREADS / 32];
    const int lane = threadIdx.x & 31;
    const int wid  = threadIdx.x >> 5;
    if (lane == 0) warp_sums[wid] = acc;
    __syncthreads();

    if (wid == 0) {
        float s = (lane < THREADS / 32) ? warp_sums[lane] : 0.0f;
        #pragma unroll
        for (int off = 4; off > 0; off >>= 1)
            s += __shfl_down_sync(0xFFFFFFFFu, s, off);

        if (lane == 0) {
            atomicAdd(&g_loss_sum, (double)s);
            __threadfence();

            // Completion counter wraps to 0 at GRID-1 (auto reset per replay).
            unsigned int prev = atomicInc(&g_done, GRID - 1);
            if (prev == GRID - 1) {
                __threadfence();
                double total = g_loss_sum;
                out[0] = (float)(total / (double)N_ROWS);
                g_loss_sum = 0.0;          // reset for next graph replay
                __threadfence();
            }
        }
    }
}

extern "C" void kernel_launch(void* const* d_in, const int* in_sizes, int n_in,
                              void* d_out, int out_size) {
    const float* X      = (const float*)d_in[0];
    const int*   target = (const int*)d_in[1];
    float*       out    = (float*)d_out;

    relu15_chunk_kernel<<<GRID, THREADS>>>(X, target, out);
}